// round 4
// baseline (speedup 1.0000x reference)
#include <cuda_runtime.h>
#include <cuda_pipeline.h>
#include <math.h>

#define RR 4
#define NN 4096
#define EE 2048
#define FF 128
#define HDIM 256
#define EW (EE/32)   // 64 mask words per node row
#define NW (NN/32)   // 128 mask words per edge row
#define PART_S4 (RR*NN*64)   // float4 stride between partial buffers

// ---------------- device scratch (allocation-free: static globals) ----------------
__device__ float    g_rw[RR];
__device__ float    g_sig[3][RR];
__device__ float    g_dv[RR*NN];
__device__ float    g_cE[RR*EE];
__device__ unsigned g_maskN[(size_t)RR*NN*EW];
__device__ unsigned g_maskE[(size_t)RR*EE*NW];
__device__ float4   g_Xs [(size_t)RR*NN*64];   // dv-scaled per-relation source
__device__ float4   g_T  [(size_t)RR*EE*64];   // edge features
__device__ float4   g_Hn [(size_t)RR*NN*64];   // per-relation node features
__device__ float4   g_pre[(size_t)NN*64];
__device__ float4   g_h  [(size_t)NN*64];
__device__ float4   g_part[(size_t)8*PART_S4]; // split-source partials (8 x 16MB)
__device__ float    g_mu[HDIM], g_var[HDIM];

// ---------------- prep ----------------
__global__ void prep_kernel(const float* __restrict__ rel, const float* __restrict__ imp) {
    if (threadIdx.x == 0) {
        float m = -1e30f;
        for (int r = 0; r < RR; r++) m = fmaxf(m, rel[r]);
        float e[RR], s = 0.f;
        for (int r = 0; r < RR; r++) { e[r] = expf(rel[r] - m); s += e[r]; }
        for (int r = 0; r < RR; r++) g_rw[r] = e[r] / s;
        for (int l = 0; l < 3; l++)
            for (int r = 0; r < RR; r++)
                g_sig[l][r] = 1.f / (1.f + expf(-imp[l*RR + r]));
    }
}

// ---------------- bitmask build: one warp per (r,n) row ----------------
__global__ void build_maskN_kernel(const float* __restrict__ H) {
    int gw   = blockIdx.x * (blockDim.x >> 5) + (threadIdx.x >> 5);
    int lane = threadIdx.x & 31;
    if (gw >= RR*NN) return;
    int r = gw / NN;
    const float* row = H + (size_t)gw * EE;
    unsigned w0 = 0, w1 = 0;
    int cnt = 0;
    #pragma unroll 8
    for (int k = 0; k < 64; k++) {
        float v = row[k*32 + lane];
        unsigned b = __ballot_sync(0xffffffffu, v != 0.0f);
        cnt += (v != 0.0f) ? 1 : 0;
        if (k == lane)      w0 = b;
        if (k == lane + 32) w1 = b;
    }
    g_maskN[(size_t)gw*EW + lane]      = w0;
    g_maskN[(size_t)gw*EW + 32 + lane] = w1;
    int tot = __reduce_add_sync(0xffffffffu, cnt);
    if (lane == 0)
        g_dv[gw] = 1.0f / sqrtf(g_rw[r] * (float)tot + 1e-8f);
}

// ---------------- 32x32 bit transpose ----------------
__global__ void transpose_mask_kernel() {
    const int tilesPerR = (NN/32)*(EE/32);
    int gw   = blockIdx.x * (blockDim.x >> 5) + (threadIdx.x >> 5);
    int lane = threadIdx.x & 31;
    if (gw >= RR * tilesPerR) return;
    int r   = gw / tilesPerR;
    int rem = gw % tilesPerR;
    int nb  = rem / (EE/32);
    int eb  = rem % (EE/32);
    unsigned w = g_maskN[((size_t)r*NN + nb*32 + lane)*EW + eb];
    unsigned out = 0;
    #pragma unroll
    for (int j = 0; j < 32; j++) {
        unsigned b = __ballot_sync(0xffffffffu, (w >> j) & 1u);
        if (lane == j) out = b;
    }
    g_maskE[((size_t)r*EE + eb*32 + lane)*NW + nb] = out;
}

// ---------------- edge constants ----------------
__global__ void build_cE_kernel() {
    int gw   = blockIdx.x * (blockDim.x >> 5) + (threadIdx.x >> 5);
    int lane = threadIdx.x & 31;
    if (gw >= RR*EE) return;
    int r = gw / EE;
    const unsigned* row = g_maskE + (size_t)gw * NW;
    int cnt = 0;
    for (int k = lane; k < NW; k += 32) cnt += __popc(row[k]);
    cnt = __reduce_add_sync(0xffffffffu, cnt);
    if (lane == 0) {
        float rw = g_rw[r];
        g_cE[gw] = rw * rw / (rw * (float)cnt + 1e-8f);
    }
}

// ---------------- pre-scale source by dv ----------------
__global__ void prescale_kernel(const float4* __restrict__ src, int srcStride4, int cshift,
                                float4* __restrict__ dst) {
    int idx = blockIdx.x*256 + threadIdx.x;
    int c  = idx & ((1<<cshift)-1);
    int rn = idx >> cshift;
    int n  = rn & (NN-1);
    float  s = g_dv[rn];
    float4 v = src[(size_t)n*srcStride4 + c];
    dst[((size_t)rn<<6) + c] = make_float4(s*v.x, s*v.y, s*v.z, s*v.w);
}

// ---------------- pipelined masked gather-SpMM (128 targets/block) ----------------
__global__ void __launch_bounds__(256) gather_kernel(
    const unsigned* __restrict__ mask, int Tn, int Sw,
    const float4* __restrict__ src, int relStride4, int srcRowStride4,
    int chunksPerP)
{
    __shared__ float4 sbuf[3*1024];   // 3 stages x 32 rows x 32 float4 = 48KB

    const int tid  = threadIdx.x, lane = tid & 31, w = tid >> 5;
    const int tilesT = Tn >> 7;
    const int r  = blockIdx.x / tilesT;
    const int t0 = (blockIdx.x % tilesT) << 7;
    const int p  = blockIdx.z;
    const int colIdx4 = (blockIdx.y << 5) + lane;
    const float4* srcB = src + (size_t)r*relStride4 + (blockIdx.y << 5);
    const int wordBase = p * chunksPerP;
    const int rowBase  = wordBase << 5;
    const unsigned* mbase = mask + ((size_t)(r*Tn + t0 + (w<<4)))*Sw + wordBase;

    auto stage = [&](int c) {
        int st = c % 3;
        int gbase = rowBase + (c << 5);
        #pragma unroll
        for (int k = 0; k < 4; k++) {
            int i = tid + (k << 8);
            int row = i >> 5, col = i & 31;
            __pipeline_memcpy_async(&sbuf[(st<<10) + (row<<5) + col],
                                    srcB + (size_t)(gbase+row)*srcRowStride4 + col, 16);
        }
        __pipeline_commit();
    };

    float4 acc[16];
    #pragma unroll
    for (int j = 0; j < 16; j++) acc[j] = make_float4(0.f,0.f,0.f,0.f);

    stage(0);
    stage(1);
    for (int c = 0; c < chunksPerP; c++) {
        __syncthreads();
        if (c + 2 < chunksPerP) stage(c+2);
        else                    __pipeline_commit();
        __pipeline_wait_prior(2);
        __syncthreads();
        const float4* bufc = sbuf + ((c % 3) << 10);
        #pragma unroll
        for (int j = 0; j < 16; j++) {
            unsigned b = mbase[(size_t)j*Sw + c];
            while (b) {
                int s = __ffs(b) - 1; b &= b - 1;
                float4 v = bufc[(s << 5) + lane];
                acc[j].x += v.x; acc[j].y += v.y; acc[j].z += v.z; acc[j].w += v.w;
            }
        }
    }

    float4* dst = g_part + (size_t)p * PART_S4;
    #pragma unroll
    for (int j = 0; j < 16; j++) {
        int t = t0 + (w<<4) + j;
        dst[((size_t)(r*Tn + t) << 6) + colIdx4] = acc[j];
    }
}

// ---------------- combine partials: out = scale * sum_p part[p] ----------------
__global__ void combine_kernel(int P, int nRows, int cshift,
                               const float* __restrict__ scale, float4* __restrict__ out) {
    int idx = blockIdx.x*256 + threadIdx.x;
    int row = idx >> cshift;
    if (row >= nRows) return;
    int c = idx & ((1<<cshift)-1);
    size_t o = ((size_t)row << 6) + c;
    float4 s = g_part[o];
    for (int p = 1; p < P; p++) {
        float4 v = g_part[(size_t)p*PART_S4 + o];
        s.x += v.x; s.y += v.y; s.z += v.z; s.w += v.w;
    }
    float sc = scale[row];
    out[o] = make_float4(sc*s.x, sc*s.y, sc*s.z, sc*s.w);
}

// ---------------- relation-summed projection GEMM (128x64 tile, 8x4/thread) ----------------
__global__ void __launch_bounds__(256) gemm_kernel(
    const float* __restrict__ A, int Fin, int Fout,
    const float* __restrict__ W,
    const float* __restrict__ sig,
    const float* __restrict__ bias,
    const float* __restrict__ resid,
    float* __restrict__ out)
{
    __shared__ float sA[16][132];   // [k][m]
    __shared__ float sB[16][72];    // [k][o]
    const int n0 = blockIdx.x << 7, o0 = blockIdx.y << 6;
    const int tid = threadIdx.x;
    const int tx = tid & 15, ty = tid >> 4;

    const int aRow = tid >> 1, aOff = (tid & 1) << 3;   // 8 A floats / thread
    const int bRow = tid >> 4, bCol = (tid & 15) << 2;  // 16x64 B tile: 1 float4 / thread

    float acc[8][4];
    #pragma unroll
    for (int i = 0; i < 8; i++)
        #pragma unroll
        for (int j = 0; j < 4; j++) acc[i][j] = 0.f;

    const int tilesPerR = Fin >> 4;
    const int nTiles = RR * tilesPerR;

    float4 aReg0, aReg1, bReg;
    {
        const float* Ap = A + (size_t)(n0+aRow)*HDIM + aOff;
        aReg0 = *(const float4*)Ap;
        aReg1 = *(const float4*)(Ap + 4);
        bReg  = *(const float4*)&W[(size_t)bRow*Fout + o0 + bCol];
    }

    for (int t = 0; t < nTiles; t++) {
        const float sr = sig[t / tilesPerR];
        sA[aOff+0][aRow] = aReg0.x; sA[aOff+1][aRow] = aReg0.y;
        sA[aOff+2][aRow] = aReg0.z; sA[aOff+3][aRow] = aReg0.w;
        sA[aOff+4][aRow] = aReg1.x; sA[aOff+5][aRow] = aReg1.y;
        sA[aOff+6][aRow] = aReg1.z; sA[aOff+7][aRow] = aReg1.w;
        *(float4*)&sB[bRow][bCol] = make_float4(sr*bReg.x, sr*bReg.y, sr*bReg.z, sr*bReg.w);
        __syncthreads();
        if (t + 1 < nTiles) {
            int t2 = t + 1;
            int r2 = t2 / tilesPerR, f2 = (t2 % tilesPerR) << 4;
            const float* Ap = A + (size_t)r2*NN*HDIM + (size_t)(n0+aRow)*HDIM + f2 + aOff;
            aReg0 = *(const float4*)Ap;
            aReg1 = *(const float4*)(Ap + 4);
            bReg  = *(const float4*)&W[(size_t)r2*Fin*Fout + (size_t)(f2+bRow)*Fout + o0 + bCol];
        }
        #pragma unroll
        for (int k = 0; k < 16; k++) {
            float4 a0 = *(const float4*)&sA[k][ty*8];
            float4 a1 = *(const float4*)&sA[k][ty*8+4];
            float4 bv = *(const float4*)&sB[k][tx*4];
            float av[8] = {a0.x,a0.y,a0.z,a0.w,a1.x,a1.y,a1.z,a1.w};
            float bb[4] = {bv.x,bv.y,bv.z,bv.w};
            #pragma unroll
            for (int i = 0; i < 8; i++)
                #pragma unroll
                for (int j = 0; j < 4; j++)
                    acc[i][j] += av[i] * bb[j];
        }
        __syncthreads();
    }

    #pragma unroll
    for (int i = 0; i < 8; i++) {
        int n = n0 + ty*8 + i;
        #pragma unroll
        for (int j = 0; j < 4; j++) {
            int o = o0 + tx*4 + j;
            float v = acc[i][j] + bias[o];
            if (resid) v += resid[(size_t)n*Fout + o];
            out[(size_t)n*Fout + o] = v;
        }
    }
}

// ---------------- BN batch statistics ----------------
__global__ void bn_stats_kernel(const float* __restrict__ X) {
    int tx = threadIdx.x & 31, ty = threadIdx.x >> 5;
    int c = blockIdx.x*32 + tx;
    float s = 0.f, sq = 0.f;
    for (int n = ty; n < NN; n += 8) {
        float v = X[(size_t)n*HDIM + c];
        s += v; sq += v*v;
    }
    __shared__ float sh1[8][32], sh2[8][32];
    sh1[ty][tx] = s; sh2[ty][tx] = sq;
    __syncthreads();
    if (ty == 0) {
        #pragma unroll
        for (int k = 1; k < 8; k++) { s += sh1[k][tx]; sq += sh2[k][tx]; }
        float mu = s / (float)NN;
        g_mu[c]  = mu;
        g_var[c] = sq / (float)NN - mu*mu;
    }
}

// ---------------- fused BN apply + LayerNorm + ELU ----------------
__global__ void bn_ln_elu_kernel(const float* __restrict__ pre,
                                 const float* __restrict__ bg, const float* __restrict__ bb,
                                 const float* __restrict__ lg, const float* __restrict__ lb,
                                 float* __restrict__ out)
{
    int n = blockIdx.x, c = threadIdx.x;
    float x = pre[(size_t)n*HDIM + c];
    x = (x - g_mu[c]) * rsqrtf(g_var[c] + 1e-5f) * bg[c] + bb[c];
    float s1 = x, s2 = x*x;
    #pragma unroll
    for (int o = 16; o > 0; o >>= 1) {
        s1 += __shfl_xor_sync(0xffffffffu, s1, o);
        s2 += __shfl_xor_sync(0xffffffffu, s2, o);
    }
    __shared__ float a1[8], a2[8];
    if ((c & 31) == 0) { a1[c>>5] = s1; a2[c>>5] = s2; }
    __syncthreads();
    s1 = 0.f; s2 = 0.f;
    #pragma unroll
    for (int k = 0; k < 8; k++) { s1 += a1[k]; s2 += a2[k]; }
    float m = s1 * (1.f/256.f);
    float v = s2 * (1.f/256.f) - m*m;
    x = (x - m) * rsqrtf(v + 1e-5f) * lg[c] + lb[c];
    out[(size_t)n*HDIM + c] = (x > 0.f) ? x : expm1f(x);
}

// ---------------- launch ----------------
extern "C" void kernel_launch(void* const* d_in, const int* in_sizes, int n_in,
                              void* d_out, int out_size) {
    const float* X    = (const float*)d_in[0];
    const float* H    = (const float*)d_in[1];
    const float* W1   = (const float*)d_in[2];
    const float* W2   = (const float*)d_in[3];
    const float* W3   = (const float*)d_in[4];
    const float* imp  = (const float*)d_in[5];
    const float* b1   = (const float*)d_in[6];
    const float* b2   = (const float*)d_in[7];
    const float* b3   = (const float*)d_in[8];
    const float* bng  = (const float*)d_in[9];
    const float* bnb  = (const float*)d_in[10];
    const float* lng  = (const float*)d_in[11];
    const float* lnb  = (const float*)d_in[12];
    const float* rel  = (const float*)d_in[13];
    float* out = (float*)d_out;

    float *pDv, *pCE, *pSig;
    float4 *pXs, *pT, *pHn, *pPre, *pH;
    unsigned *pMN, *pME;
    cudaGetSymbolAddress((void**)&pDv, g_dv);
    cudaGetSymbolAddress((void**)&pCE, g_cE);
    cudaGetSymbolAddress((void**)&pSig,g_sig);
    cudaGetSymbolAddress((void**)&pXs, g_Xs);
    cudaGetSymbolAddress((void**)&pT,  g_T);
    cudaGetSymbolAddress((void**)&pHn, g_Hn);
    cudaGetSymbolAddress((void**)&pPre,g_pre);
    cudaGetSymbolAddress((void**)&pH,  g_h);
    cudaGetSymbolAddress((void**)&pMN, g_maskN);
    cudaGetSymbolAddress((void**)&pME, g_maskE);

    // ---- structure precompute ----
    prep_kernel<<<1, 32>>>(rel, imp);
    build_maskN_kernel<<<RR*NN/8, 256>>>(H);
    transpose_mask_kernel<<<RR*(NN/32)*(EE/32)/8, 256>>>();
    build_cE_kernel<<<RR*EE/8, 256>>>();

    const int tE = EE/128, tN = NN/128;   // 16, 32

    // ---- layer 1 (128 cols) ----
    prescale_kernel<<<RR*NN*32/256, 256>>>((const float4*)X, 32, 5, pXs);
    gather_kernel<<<dim3(RR*tE, 1, 8), 256>>>(pME, EE, NW, pXs, NN*64, 64, NW/8);
    combine_kernel<<<RR*EE*32/256, 256>>>(8, RR*EE, 5, pCE, pT);
    gather_kernel<<<dim3(RR*tN, 1, 4), 256>>>(pMN, NN, EW, pT, EE*64, 64, EW/4);
    combine_kernel<<<RR*NN*32/256, 256>>>(4, RR*NN, 5, pDv, pHn);
    gemm_kernel<<<dim3(NN/128, HDIM/64), 256>>>((const float*)pHn, FF, HDIM, W1, pSig + 0*RR, b1, nullptr, (float*)pPre);
    bn_stats_kernel<<<HDIM/32, 256>>>((const float*)pPre);
    bn_ln_elu_kernel<<<NN, HDIM>>>((const float*)pPre, bng, bnb, lng, lnb, (float*)pH);

    // ---- layer 2 (256 cols) ----
    prescale_kernel<<<RR*NN*64/256, 256>>>(pH, 64, 6, pXs);
    gather_kernel<<<dim3(RR*tE, 2, 4), 256>>>(pME, EE, NW, pXs, NN*64, 64, NW/4);
    combine_kernel<<<RR*EE*64/256, 256>>>(4, RR*EE, 6, pCE, pT);
    gather_kernel<<<dim3(RR*tN, 2, 2), 256>>>(pMN, NN, EW, pT, EE*64, 64, EW/2);
    combine_kernel<<<RR*NN*64/256, 256>>>(2, RR*NN, 6, pDv, pHn);
    gemm_kernel<<<dim3(NN/128, HDIM/64), 256>>>((const float*)pHn, HDIM, HDIM, W2, pSig + 1*RR, b2, nullptr, (float*)pPre);
    bn_stats_kernel<<<HDIM/32, 256>>>((const float*)pPre);
    bn_ln_elu_kernel<<<NN, HDIM>>>((const float*)pPre, bng + HDIM, bnb + HDIM, lng + HDIM, lnb + HDIM, (float*)pH);

    // ---- layer 3 (256 cols) + residual ----
    prescale_kernel<<<RR*NN*64/256, 256>>>(pH, 64, 6, pXs);
    gather_kernel<<<dim3(RR*tE, 2, 4), 256>>>(pME, EE, NW, pXs, NN*64, 64, NW/4);
    combine_kernel<<<RR*EE*64/256, 256>>>(4, RR*EE, 6, pCE, pT);
    gather_kernel<<<dim3(RR*tN, 2, 2), 256>>>(pMN, NN, EW, pT, EE*64, 64, EW/2);
    combine_kernel<<<RR*NN*64/256, 256>>>(2, RR*NN, 6, pDv, pHn);
    gemm_kernel<<<dim3(NN/128, FF/64), 256>>>((const float*)pHn, HDIM, FF, W3, pSig + 2*RR, b3, X, out);
}

// round 5
// speedup vs baseline: 1.4063x; 1.4063x over previous
#include <cuda_runtime.h>
#include <cuda_pipeline.h>
#include <math.h>

#define RR 4
#define NN 4096
#define EE 2048
#define FF 128
#define HDIM 256
#define EW (EE/32)   // 64 mask words per node row
#define NW (NN/32)   // 128 mask words per edge row
#define PART_S4 (RR*NN*64)   // float4 stride between partial buffers

// ---------------- device scratch ----------------
__device__ float    g_rw[RR];
__device__ float    g_sig[3][RR];
__device__ float    g_dv[RR*NN];
__device__ float    g_cE[RR*EE];
__device__ unsigned g_maskN[(size_t)RR*NN*EW];
__device__ unsigned g_maskE[(size_t)RR*EE*NW];
__device__ float4   g_Xs [(size_t)RR*NN*64];
__device__ float4   g_T  [(size_t)RR*EE*64];
__device__ float4   g_Hn [(size_t)RR*NN*64];
__device__ float4   g_pre[(size_t)NN*64];
__device__ float4   g_h  [(size_t)NN*64];
__device__ float4   g_part[(size_t)4*PART_S4];
__device__ float    g_mu[HDIM], g_var[HDIM];

// ---------------- prep ----------------
__global__ void prep_kernel(const float* __restrict__ rel, const float* __restrict__ imp) {
    if (threadIdx.x == 0) {
        float m = -1e30f;
        for (int r = 0; r < RR; r++) m = fmaxf(m, rel[r]);
        float e[RR], s = 0.f;
        for (int r = 0; r < RR; r++) { e[r] = expf(rel[r] - m); s += e[r]; }
        for (int r = 0; r < RR; r++) g_rw[r] = e[r] / s;
        for (int l = 0; l < 3; l++)
            for (int r = 0; r < RR; r++)
                g_sig[l][r] = 1.f / (1.f + expf(-imp[l*RR + r]));
    }
}

// ---------------- bitmask build ----------------
__global__ void build_maskN_kernel(const float* __restrict__ H) {
    int gw   = blockIdx.x * (blockDim.x >> 5) + (threadIdx.x >> 5);
    int lane = threadIdx.x & 31;
    if (gw >= RR*NN) return;
    int r = gw / NN;
    const float* row = H + (size_t)gw * EE;
    unsigned w0 = 0, w1 = 0;
    int cnt = 0;
    #pragma unroll 8
    for (int k = 0; k < 64; k++) {
        float v = row[k*32 + lane];
        unsigned b = __ballot_sync(0xffffffffu, v != 0.0f);
        cnt += (v != 0.0f) ? 1 : 0;
        if (k == lane)      w0 = b;
        if (k == lane + 32) w1 = b;
    }
    g_maskN[(size_t)gw*EW + lane]      = w0;
    g_maskN[(size_t)gw*EW + 32 + lane] = w1;
    int tot = __reduce_add_sync(0xffffffffu, cnt);
    if (lane == 0)
        g_dv[gw] = 1.0f / sqrtf(g_rw[r] * (float)tot + 1e-8f);
}

// ---------------- 32x32 bit transpose ----------------
__global__ void transpose_mask_kernel() {
    const int tilesPerR = (NN/32)*(EE/32);
    int gw   = blockIdx.x * (blockDim.x >> 5) + (threadIdx.x >> 5);
    int lane = threadIdx.x & 31;
    if (gw >= RR * tilesPerR) return;
    int r   = gw / tilesPerR;
    int rem = gw % tilesPerR;
    int nb  = rem / (EE/32);
    int eb  = rem % (EE/32);
    unsigned w = g_maskN[((size_t)r*NN + nb*32 + lane)*EW + eb];
    unsigned out = 0;
    #pragma unroll
    for (int j = 0; j < 32; j++) {
        unsigned b = __ballot_sync(0xffffffffu, (w >> j) & 1u);
        if (lane == j) out = b;
    }
    g_maskE[((size_t)r*EE + eb*32 + lane)*NW + nb] = out;
}

// ---------------- edge constants ----------------
__global__ void build_cE_kernel() {
    int gw   = blockIdx.x * (blockDim.x >> 5) + (threadIdx.x >> 5);
    int lane = threadIdx.x & 31;
    if (gw >= RR*EE) return;
    int r = gw / EE;
    const unsigned* row = g_maskE + (size_t)gw * NW;
    int cnt = 0;
    for (int k = lane; k < NW; k += 32) cnt += __popc(row[k]);
    cnt = __reduce_add_sync(0xffffffffu, cnt);
    if (lane == 0) {
        float rw = g_rw[r];
        g_cE[gw] = rw * rw / (rw * (float)cnt + 1e-8f);
    }
}

// ---------------- pre-scale source by dv ----------------
__global__ void prescale_kernel(const float4* __restrict__ src, int srcStride4, int cshift,
                                float4* __restrict__ dst) {
    int idx = blockIdx.x*256 + threadIdx.x;
    int c  = idx & ((1<<cshift)-1);
    int rn = idx >> cshift;
    int n  = rn & (NN-1);
    float  s = g_dv[rn];
    float4 v = src[(size_t)n*srcStride4 + c];
    dst[((size_t)rn<<6) + c] = make_float4(s*v.x, s*v.y, s*v.z, s*v.w);
}

// ---------------- pipelined masked gather-SpMM (R2 config: 64 targets/block) ----------------
__global__ void __launch_bounds__(256) gather_kernel(
    const unsigned* __restrict__ mask, int Tn, int Sw,
    const float4* __restrict__ src, int relStride4, int srcRowStride4,
    int chunksPerP,
    const float* __restrict__ outScale,
    float4* __restrict__ out)
{
    __shared__ float4 sbuf[3*1024];   // 3 stages x 32 rows x 32 float4 = 48KB

    const int tid  = threadIdx.x, lane = tid & 31, w = tid >> 5;
    const int tilesT = Tn >> 6;
    const int r  = blockIdx.x / tilesT;
    const int t0 = (blockIdx.x % tilesT) << 6;
    const int p  = blockIdx.z;
    const int colIdx4 = (blockIdx.y << 5) + lane;
    const float4* srcB = src + (size_t)r*relStride4 + (blockIdx.y << 5);
    const int wordBase = p * chunksPerP;
    const int rowBase  = wordBase << 5;
    const unsigned* mbase = mask + ((size_t)(r*Tn + t0 + (w<<3)))*Sw + wordBase;

    auto stage = [&](int c) {
        int st = c % 3;
        int gbase = rowBase + (c << 5);
        #pragma unroll
        for (int k = 0; k < 4; k++) {
            int i = tid + (k << 8);
            int row = i >> 5, col = i & 31;
            __pipeline_memcpy_async(&sbuf[(st<<10) + (row<<5) + col],
                                    srcB + (size_t)(gbase+row)*srcRowStride4 + col, 16);
        }
        __pipeline_commit();
    };

    float4 acc[8];
    #pragma unroll
    for (int j = 0; j < 8; j++) acc[j] = make_float4(0.f,0.f,0.f,0.f);

    stage(0);
    stage(1);
    for (int c = 0; c < chunksPerP; c++) {
        __syncthreads();
        if (c + 2 < chunksPerP) stage(c+2);
        else                    __pipeline_commit();
        __pipeline_wait_prior(2);
        __syncthreads();
        const float4* bufc = sbuf + ((c % 3) << 10);
        #pragma unroll
        for (int j = 0; j < 8; j++) {
            unsigned b = mbase[(size_t)j*Sw + c];
            while (b) {
                int s = __ffs(b) - 1; b &= b - 1;
                float4 v = bufc[(s << 5) + lane];
                acc[j].x += v.x; acc[j].y += v.y; acc[j].z += v.z; acc[j].w += v.w;
            }
        }
    }

    float4* dst = outScale ? out : (g_part + (size_t)p * PART_S4);
    #pragma unroll
    for (int j = 0; j < 8; j++) {
        int t = t0 + (w<<3) + j;
        size_t o = ((size_t)(r*Tn + t) << 6) + colIdx4;
        float4 v = acc[j];
        if (outScale) {
            float sc = outScale[r*Tn + t];
            v.x *= sc; v.y *= sc; v.z *= sc; v.w *= sc;
        }
        dst[o] = v;
    }
}

// ---------------- combine partials ----------------
__global__ void combine_kernel(int P, int nRows, int cshift,
                               const float* __restrict__ scale, float4* __restrict__ out) {
    int idx = blockIdx.x*256 + threadIdx.x;
    int row = idx >> cshift;
    if (row >= nRows) return;
    int c = idx & ((1<<cshift)-1);
    size_t o = ((size_t)row << 6) + c;
    float4 s = g_part[o];
    for (int p = 1; p < P; p++) {
        float4 v = g_part[(size_t)p*PART_S4 + o];
        s.x += v.x; s.y += v.y; s.z += v.z; s.w += v.w;
    }
    float sc = scale[row];
    out[o] = make_float4(sc*s.x, sc*s.y, sc*s.z, sc*s.w);
}

// ---------------- relation-summed projection GEMM (128x64 tile, 8x4/thread) ----------------
__global__ void __launch_bounds__(256) gemm_kernel(
    const float* __restrict__ A, int Fin, int Fout,
    const float* __restrict__ W,
    const float* __restrict__ sig,
    const float* __restrict__ bias,
    const float* __restrict__ resid,
    float* __restrict__ out)
{
    __shared__ float sA[16][132];   // [k][m]
    __shared__ float sB[16][72];    // [k][o]
    const int n0 = blockIdx.x << 7, o0 = blockIdx.y << 6;
    const int tid = threadIdx.x;
    const int tx = tid & 15, ty = tid >> 4;

    const int aRow = tid >> 1, aOff = (tid & 1) << 3;   // 8 A floats / thread
    const int bRow = tid >> 4, bCol = (tid & 15) << 2;  // 16x64 B tile: 1 float4 / thread

    float acc[8][4];
    #pragma unroll
    for (int i = 0; i < 8; i++)
        #pragma unroll
        for (int j = 0; j < 4; j++) acc[i][j] = 0.f;

    const int tilesPerR = Fin >> 4;
    const int nTiles = RR * tilesPerR;

    float4 aReg0, aReg1, bReg;
    {
        const float* Ap = A + (size_t)(n0+aRow)*HDIM + aOff;
        aReg0 = *(const float4*)Ap;
        aReg1 = *(const float4*)(Ap + 4);
        bReg  = *(const float4*)&W[(size_t)bRow*Fout + o0 + bCol];
    }

    for (int t = 0; t < nTiles; t++) {
        const float sr = sig[t / tilesPerR];
        sA[aOff+0][aRow] = aReg0.x; sA[aOff+1][aRow] = aReg0.y;
        sA[aOff+2][aRow] = aReg0.z; sA[aOff+3][aRow] = aReg0.w;
        sA[aOff+4][aRow] = aReg1.x; sA[aOff+5][aRow] = aReg1.y;
        sA[aOff+6][aRow] = aReg1.z; sA[aOff+7][aRow] = aReg1.w;
        *(float4*)&sB[bRow][bCol] = make_float4(sr*bReg.x, sr*bReg.y, sr*bReg.z, sr*bReg.w);
        __syncthreads();
        if (t + 1 < nTiles) {
            int t2 = t + 1;
            int r2 = t2 / tilesPerR, f2 = (t2 % tilesPerR) << 4;
            const float* Ap = A + (size_t)r2*NN*HDIM + (size_t)(n0+aRow)*HDIM + f2 + aOff;
            aReg0 = *(const float4*)Ap;
            aReg1 = *(const float4*)(Ap + 4);
            bReg  = *(const float4*)&W[(size_t)r2*Fin*Fout + (size_t)(f2+bRow)*Fout + o0 + bCol];
        }
        #pragma unroll
        for (int k = 0; k < 16; k++) {
            float4 a0 = *(const float4*)&sA[k][ty*8];
            float4 a1 = *(const float4*)&sA[k][ty*8+4];
            float4 bv = *(const float4*)&sB[k][tx*4];
            float av[8] = {a0.x,a0.y,a0.z,a0.w,a1.x,a1.y,a1.z,a1.w};
            float bb[4] = {bv.x,bv.y,bv.z,bv.w};
            #pragma unroll
            for (int i = 0; i < 8; i++)
                #pragma unroll
                for (int j = 0; j < 4; j++)
                    acc[i][j] += av[i] * bb[j];
        }
        __syncthreads();
    }

    #pragma unroll
    for (int i = 0; i < 8; i++) {
        int n = n0 + ty*8 + i;
        #pragma unroll
        for (int j = 0; j < 4; j++) {
            int o = o0 + tx*4 + j;
            float v = acc[i][j] + bias[o];
            if (resid) v += resid[(size_t)n*Fout + o];
            out[(size_t)n*Fout + o] = v;
        }
    }
}

// ---------------- BN batch statistics ----------------
__global__ void bn_stats_kernel(const float* __restrict__ X) {
    int tx = threadIdx.x & 31, ty = threadIdx.x >> 5;
    int c = blockIdx.x*32 + tx;
    float s = 0.f, sq = 0.f;
    for (int n = ty; n < NN; n += 8) {
        float v = X[(size_t)n*HDIM + c];
        s += v; sq += v*v;
    }
    __shared__ float sh1[8][32], sh2[8][32];
    sh1[ty][tx] = s; sh2[ty][tx] = sq;
    __syncthreads();
    if (ty == 0) {
        #pragma unroll
        for (int k = 1; k < 8; k++) { s += sh1[k][tx]; sq += sh2[k][tx]; }
        float mu = s / (float)NN;
        g_mu[c]  = mu;
        g_var[c] = sq / (float)NN - mu*mu;
    }
}

// ---------------- fused BN apply + LayerNorm + ELU ----------------
__global__ void bn_ln_elu_kernel(const float* __restrict__ pre,
                                 const float* __restrict__ bg, const float* __restrict__ bb,
                                 const float* __restrict__ lg, const float* __restrict__ lb,
                                 float* __restrict__ out)
{
    int n = blockIdx.x, c = threadIdx.x;
    float x = pre[(size_t)n*HDIM + c];
    x = (x - g_mu[c]) * rsqrtf(g_var[c] + 1e-5f) * bg[c] + bb[c];
    float s1 = x, s2 = x*x;
    #pragma unroll
    for (int o = 16; o > 0; o >>= 1) {
        s1 += __shfl_xor_sync(0xffffffffu, s1, o);
        s2 += __shfl_xor_sync(0xffffffffu, s2, o);
    }
    __shared__ float a1[8], a2[8];
    if ((c & 31) == 0) { a1[c>>5] = s1; a2[c>>5] = s2; }
    __syncthreads();
    s1 = 0.f; s2 = 0.f;
    #pragma unroll
    for (int k = 0; k < 8; k++) { s1 += a1[k]; s2 += a2[k]; }
    float m = s1 * (1.f/256.f);
    float v = s2 * (1.f/256.f) - m*m;
    x = (x - m) * rsqrtf(v + 1e-5f) * lg[c] + lb[c];
    out[(size_t)n*HDIM + c] = (x > 0.f) ? x : expm1f(x);
}

// ---------------- launch ----------------
extern "C" void kernel_launch(void* const* d_in, const int* in_sizes, int n_in,
                              void* d_out, int out_size) {
    const float* X    = (const float*)d_in[0];
    const float* H    = (const float*)d_in[1];
    const float* W1   = (const float*)d_in[2];
    const float* W2   = (const float*)d_in[3];
    const float* W3   = (const float*)d_in[4];
    const float* imp  = (const float*)d_in[5];
    const float* b1   = (const float*)d_in[6];
    const float* b2   = (const float*)d_in[7];
    const float* b3   = (const float*)d_in[8];
    const float* bng  = (const float*)d_in[9];
    const float* bnb  = (const float*)d_in[10];
    const float* lng  = (const float*)d_in[11];
    const float* lnb  = (const float*)d_in[12];
    const float* rel  = (const float*)d_in[13];
    float* out = (float*)d_out;

    float *pDv, *pCE, *pSig;
    float4 *pXs, *pT, *pHn, *pPre, *pH;
    unsigned *pMN, *pME;
    cudaGetSymbolAddress((void**)&pDv, g_dv);
    cudaGetSymbolAddress((void**)&pCE, g_cE);
    cudaGetSymbolAddress((void**)&pSig,g_sig);
    cudaGetSymbolAddress((void**)&pXs, g_Xs);
    cudaGetSymbolAddress((void**)&pT,  g_T);
    cudaGetSymbolAddress((void**)&pHn, g_Hn);
    cudaGetSymbolAddress((void**)&pPre,g_pre);
    cudaGetSymbolAddress((void**)&pH,  g_h);
    cudaGetSymbolAddress((void**)&pMN, g_maskN);
    cudaGetSymbolAddress((void**)&pME, g_maskE);

    // ---- structure precompute ----
    prep_kernel<<<1, 32>>>(rel, imp);
    build_maskN_kernel<<<RR*NN/8, 256>>>(H);
    transpose_mask_kernel<<<RR*(NN/32)*(EE/32)/8, 256>>>();
    build_cE_kernel<<<RR*EE/8, 256>>>();

    const int tilesE = EE/64, tilesN = NN/64;   // 32, 64

    // ---- layer 1 (cols = 128 -> colb 1, cshift 5) ----
    prescale_kernel<<<RR*NN*32/256, 256>>>((const float4*)X, 32, 5, pXs);
    gather_kernel<<<dim3(RR*tilesE, 1, 4), 256>>>(pME, EE, NW, pXs, NN*64, 64, (NN/32)/4, nullptr, nullptr);
    combine_kernel<<<RR*EE*32/256, 256>>>(4, RR*EE, 5, pCE, pT);
    gather_kernel<<<dim3(RR*tilesN, 1, 2), 256>>>(pMN, NN, EW, pT, EE*64, 64, (EE/32)/2, nullptr, nullptr);
    combine_kernel<<<RR*NN*32/256, 256>>>(2, RR*NN, 5, pDv, pHn);
    gemm_kernel<<<dim3(NN/128, HDIM/64), 256>>>((const float*)pHn, FF, HDIM, W1, pSig + 0*RR, b1, nullptr, (float*)pPre);
    bn_stats_kernel<<<HDIM/32, 256>>>((const float*)pPre);
    bn_ln_elu_kernel<<<NN, HDIM>>>((const float*)pPre, bng, bnb, lng, lnb, (float*)pH);

    // ---- layer 2 (cols = 256 -> colb 2, cshift 6) ----
    prescale_kernel<<<RR*NN*64/256, 256>>>(pH, 64, 6, pXs);
    gather_kernel<<<dim3(RR*tilesE, 2, 2), 256>>>(pME, EE, NW, pXs, NN*64, 64, (NN/32)/2, nullptr, nullptr);
    combine_kernel<<<RR*EE*64/256, 256>>>(2, RR*EE, 6, pCE, pT);
    gather_kernel<<<dim3(RR*tilesN, 2, 1), 256>>>(pMN, NN, EW, pT, EE*64, 64, (EE/32), pDv, pHn);
    gemm_kernel<<<dim3(NN/128, HDIM/64), 256>>>((const float*)pHn, HDIM, HDIM, W2, pSig + 1*RR, b2, nullptr, (float*)pPre);
    bn_stats_kernel<<<HDIM/32, 256>>>((const float*)pPre);
    bn_ln_elu_kernel<<<NN, HDIM>>>((const float*)pPre, bng + HDIM, bnb + HDIM, lng + HDIM, lnb + HDIM, (float*)pH);

    // ---- layer 3 (cols = 256) + residual ----
    prescale_kernel<<<RR*NN*64/256, 256>>>(pH, 64, 6, pXs);
    gather_kernel<<<dim3(RR*tilesE, 2, 2), 256>>>(pME, EE, NW, pXs, NN*64, 64, (NN/32)/2, nullptr, nullptr);
    combine_kernel<<<RR*EE*64/256, 256>>>(2, RR*EE, 6, pCE, pT);
    gather_kernel<<<dim3(RR*tilesN, 2, 1), 256>>>(pMN, NN, EW, pT, EE*64, 64, (EE/32), pDv, pHn);
    gemm_kernel<<<dim3(NN/128, FF/64), 256>>>((const float*)pHn, HDIM, FF, W3, pSig + 2*RR, b3, X, out);
}

// round 6
// speedup vs baseline: 1.6235x; 1.1544x over previous
#include <cuda_runtime.h>
#include <cuda_pipeline.h>
#include <math.h>

#define RR 4
#define NN 4096
#define EE 2048
#define FF 128
#define HDIM 256
#define EW (EE/32)
#define NW (NN/32)
#define PART_S4 (RR*NN*64)   // float4 stride between partial buffers

// ---------------- device scratch ----------------
__device__ float    g_rw[RR];
__device__ float    g_sig[3][RR];
__device__ float    g_dv[RR*NN];
__device__ float    g_cE[RR*EE];
__device__ unsigned g_maskN[(size_t)RR*NN*EW];
__device__ unsigned g_maskE[(size_t)RR*EE*NW];
__device__ float4   g_Xs [(size_t)RR*NN*64];
__device__ float4   g_T  [(size_t)RR*EE*64];
__device__ float4   g_Hn [(size_t)RR*NN*64];
__device__ float4   g_pre[(size_t)NN*64];
__device__ float4   g_h  [(size_t)NN*64];
__device__ float4   g_part[(size_t)4*PART_S4];
__device__ float    g_mu[HDIM], g_var[HDIM];
__device__ float    g_bnp[2][8][HDIM];

// ---------------- prep ----------------
__global__ void prep_kernel(const float* __restrict__ rel, const float* __restrict__ imp) {
    if (threadIdx.x == 0) {
        float m = -1e30f;
        for (int r = 0; r < RR; r++) m = fmaxf(m, rel[r]);
        float e[RR], s = 0.f;
        for (int r = 0; r < RR; r++) { e[r] = expf(rel[r] - m); s += e[r]; }
        for (int r = 0; r < RR; r++) g_rw[r] = e[r] / s;
        for (int l = 0; l < 3; l++)
            for (int r = 0; r < RR; r++)
                g_sig[l][r] = 1.f / (1.f + expf(-imp[l*RR + r]));
    }
}

// ---------------- bitmask build ----------------
__global__ void build_maskN_kernel(const float* __restrict__ H) {
    int gw   = blockIdx.x * (blockDim.x >> 5) + (threadIdx.x >> 5);
    int lane = threadIdx.x & 31;
    if (gw >= RR*NN) return;
    int r = gw / NN;
    const float* row = H + (size_t)gw * EE;
    unsigned w0 = 0, w1 = 0;
    int cnt = 0;
    #pragma unroll 8
    for (int k = 0; k < 64; k++) {
        float v = row[k*32 + lane];
        unsigned b = __ballot_sync(0xffffffffu, v != 0.0f);
        cnt += (v != 0.0f) ? 1 : 0;
        if (k == lane)      w0 = b;
        if (k == lane + 32) w1 = b;
    }
    g_maskN[(size_t)gw*EW + lane]      = w0;
    g_maskN[(size_t)gw*EW + 32 + lane] = w1;
    int tot = __reduce_add_sync(0xffffffffu, cnt);
    if (lane == 0)
        g_dv[gw] = 1.0f / sqrtf(g_rw[r] * (float)tot + 1e-8f);
}

// ---------------- 32x32 bit transpose ----------------
__global__ void transpose_mask_kernel() {
    const int tilesPerR = (NN/32)*(EE/32);
    int gw   = blockIdx.x * (blockDim.x >> 5) + (threadIdx.x >> 5);
    int lane = threadIdx.x & 31;
    if (gw >= RR * tilesPerR) return;
    int r   = gw / tilesPerR;
    int rem = gw % tilesPerR;
    int nb  = rem / (EE/32);
    int eb  = rem % (EE/32);
    unsigned w = g_maskN[((size_t)r*NN + nb*32 + lane)*EW + eb];
    unsigned out = 0;
    #pragma unroll
    for (int j = 0; j < 32; j++) {
        unsigned b = __ballot_sync(0xffffffffu, (w >> j) & 1u);
        if (lane == j) out = b;
    }
    g_maskE[((size_t)r*EE + eb*32 + lane)*NW + nb] = out;
}

// ---------------- edge constants ----------------
__global__ void build_cE_kernel() {
    int gw   = blockIdx.x * (blockDim.x >> 5) + (threadIdx.x >> 5);
    int lane = threadIdx.x & 31;
    if (gw >= RR*EE) return;
    int r = gw / EE;
    const unsigned* row = g_maskE + (size_t)gw * NW;
    int cnt = 0;
    for (int k = lane; k < NW; k += 32) cnt += __popc(row[k]);
    cnt = __reduce_add_sync(0xffffffffu, cnt);
    if (lane == 0) {
        float rw = g_rw[r];
        g_cE[gw] = rw * rw / (rw * (float)cnt + 1e-8f);
    }
}

// ---------------- pre-scale source by dv ----------------
__global__ void prescale_kernel(const float4* __restrict__ src, int srcStride4, int cshift,
                                float4* __restrict__ dst) {
    int idx = blockIdx.x*256 + threadIdx.x;
    int c  = idx & ((1<<cshift)-1);
    int rn = idx >> cshift;
    int n  = rn & (NN-1);
    float  s = g_dv[rn];
    float4 v = src[(size_t)n*srcStride4 + c];
    dst[((size_t)rn<<6) + c] = make_float4(s*v.x, s*v.y, s*v.z, s*v.w);
}

// ---------------- pipelined masked gather-SpMM: 512 threads, 128 targets/block ----------------
__global__ void __launch_bounds__(512) gather_kernel(
    const unsigned* __restrict__ mask, int Tn, int Sw,
    const float4* __restrict__ src, int relStride4, int srcRowStride4,
    int chunksPerP,
    const float* __restrict__ outScale,
    float4* __restrict__ out)
{
    __shared__ float4 sbuf[3*1024];   // 3 stages x 32 rows x 32 float4 = 48KB

    const int tid  = threadIdx.x, lane = tid & 31, w = tid >> 5;  // 16 warps
    const int tilesT = Tn >> 7;
    const int r  = blockIdx.x / tilesT;
    const int t0 = (blockIdx.x % tilesT) << 7;
    const int p  = blockIdx.z;
    const int colIdx4 = (blockIdx.y << 5) + lane;
    const float4* srcB = src + (size_t)r*relStride4 + (blockIdx.y << 5);
    const int wordBase = p * chunksPerP;
    const int rowBase  = wordBase << 5;
    const unsigned* mbase = mask + ((size_t)(r*Tn + t0 + (w<<3)))*Sw + wordBase;

    auto stage = [&](int c) {
        int st = c % 3;
        int gbase = rowBase + (c << 5);
        #pragma unroll
        for (int k = 0; k < 2; k++) {
            int i = tid + (k << 9);
            int row = i >> 5, col = i & 31;
            __pipeline_memcpy_async(&sbuf[(st<<10) + (row<<5) + col],
                                    srcB + (size_t)(gbase+row)*srcRowStride4 + col, 16);
        }
        __pipeline_commit();
    };

    float4 acc[8];
    #pragma unroll
    for (int j = 0; j < 8; j++) acc[j] = make_float4(0.f,0.f,0.f,0.f);

    stage(0);
    stage(1);
    for (int c = 0; c < chunksPerP; c++) {
        __syncthreads();
        if (c + 2 < chunksPerP) stage(c+2);
        else                    __pipeline_commit();
        __pipeline_wait_prior(2);
        __syncthreads();
        const float4* bufc = sbuf + ((c % 3) << 10);
        #pragma unroll
        for (int j = 0; j < 8; j++) {
            unsigned b = mbase[(size_t)j*Sw + c];
            while (b) {
                int s = __ffs(b) - 1; b &= b - 1;
                float4 v = bufc[(s << 5) + lane];
                acc[j].x += v.x; acc[j].y += v.y; acc[j].z += v.z; acc[j].w += v.w;
            }
        }
    }

    float4* dst = outScale ? out : (g_part + (size_t)p * PART_S4);
    #pragma unroll
    for (int j = 0; j < 8; j++) {
        int t = t0 + (w<<3) + j;
        size_t o = ((size_t)(r*Tn + t) << 6) + colIdx4;
        float4 v = acc[j];
        if (outScale) {
            float sc = outScale[r*Tn + t];
            v.x *= sc; v.y *= sc; v.z *= sc; v.w *= sc;
        }
        dst[o] = v;
    }
}

// ---------------- combine gather partials ----------------
__global__ void combine_kernel(int P, int nRows, int cshift,
                               const float* __restrict__ scale, float4* __restrict__ out) {
    int idx = blockIdx.x*256 + threadIdx.x;
    int row = idx >> cshift;
    if (row >= nRows) return;
    int c = idx & ((1<<cshift)-1);
    size_t o = ((size_t)row << 6) + c;
    float4 s = g_part[o];
    for (int p = 1; p < P; p++) {
        float4 v = g_part[(size_t)p*PART_S4 + o];
        s.x += v.x; s.y += v.y; s.z += v.z; s.w += v.w;
    }
    float sc = scale[row];
    out[o] = make_float4(sc*s.x, sc*s.y, sc*s.z, sc*s.w);
}

// ---------------- per-relation projection GEMM (128x64 tile, r = blockIdx.z) ----------------
// writes raw partial: part[r][n][o] = sum_f A[r][n][f]*W[r][f][o]
__global__ void __launch_bounds__(256) gemm_kernel(
    const float* __restrict__ A, int Fin, int Fout,
    const float* __restrict__ W,
    float* __restrict__ part)
{
    __shared__ float sA[16][132];
    __shared__ float sB[16][72];
    const int n0 = blockIdx.x << 7, o0 = blockIdx.y << 6;
    const int rr = blockIdx.z;
    const int tid = threadIdx.x;
    const int tx = tid & 15, ty = tid >> 4;

    const int aRow = tid >> 1, aOff = (tid & 1) << 3;
    const int bRow = tid >> 4, bCol = (tid & 15) << 2;

    const float* Ar = A + (size_t)rr*NN*HDIM;
    const float* Wr = W + (size_t)rr*Fin*Fout;

    float acc[8][4];
    #pragma unroll
    for (int i = 0; i < 8; i++)
        #pragma unroll
        for (int j = 0; j < 4; j++) acc[i][j] = 0.f;

    const int nTiles = Fin >> 4;

    float4 aReg0, aReg1, bReg;
    {
        const float* Ap = Ar + (size_t)(n0+aRow)*HDIM + aOff;
        aReg0 = *(const float4*)Ap;
        aReg1 = *(const float4*)(Ap + 4);
        bReg  = *(const float4*)&Wr[(size_t)bRow*Fout + o0 + bCol];
    }

    for (int t = 0; t < nTiles; t++) {
        sA[aOff+0][aRow] = aReg0.x; sA[aOff+1][aRow] = aReg0.y;
        sA[aOff+2][aRow] = aReg0.z; sA[aOff+3][aRow] = aReg0.w;
        sA[aOff+4][aRow] = aReg1.x; sA[aOff+5][aRow] = aReg1.y;
        sA[aOff+6][aRow] = aReg1.z; sA[aOff+7][aRow] = aReg1.w;
        *(float4*)&sB[bRow][bCol] = bReg;
        __syncthreads();
        if (t + 1 < nTiles) {
            int f2 = (t + 1) << 4;
            const float* Ap = Ar + (size_t)(n0+aRow)*HDIM + f2 + aOff;
            aReg0 = *(const float4*)Ap;
            aReg1 = *(const float4*)(Ap + 4);
            bReg  = *(const float4*)&Wr[(size_t)(f2+bRow)*Fout + o0 + bCol];
        }
        #pragma unroll
        for (int k = 0; k < 16; k++) {
            float4 a0 = *(const float4*)&sA[k][ty*8];
            float4 a1 = *(const float4*)&sA[k][ty*8+4];
            float4 bv = *(const float4*)&sB[k][tx*4];
            float av[8] = {a0.x,a0.y,a0.z,a0.w,a1.x,a1.y,a1.z,a1.w};
            float bb[4] = {bv.x,bv.y,bv.z,bv.w};
            #pragma unroll
            for (int i = 0; i < 8; i++)
                #pragma unroll
                for (int j = 0; j < 4; j++)
                    acc[i][j] += av[i] * bb[j];
        }
        __syncthreads();
    }

    float* dst = part + (size_t)rr*NN*256;
    #pragma unroll
    for (int i = 0; i < 8; i++) {
        int n = n0 + ty*8 + i;
        #pragma unroll
        for (int j = 0; j < 4; j++) {
            int o = o0 + tx*4 + j;
            dst[(size_t)n*Fout + o] = acc[i][j];
        }
    }
}

// ---------------- gemm combine: out = sum_r sig[r]*part[r] + bias (+resid) ----------------
__global__ void gemm_combine_kernel(const float* __restrict__ part, int Fout4,
                                    const float* __restrict__ sig,
                                    const float* __restrict__ bias,
                                    const float* __restrict__ resid,
                                    float* __restrict__ out)
{
    int idx = blockIdx.x*256 + threadIdx.x;   // over NN*Fout4
    int o4 = idx % Fout4, n = idx / Fout4;
    float4 s = make_float4(0.f,0.f,0.f,0.f);
    #pragma unroll
    for (int r = 0; r < RR; r++) {
        float sr = sig[r];
        float4 v = *(const float4*)&part[(size_t)r*NN*256 + (size_t)n*(Fout4*4) + o4*4];
        s.x += sr*v.x; s.y += sr*v.y; s.z += sr*v.z; s.w += sr*v.w;
    }
    float4 b = ((const float4*)bias)[o4];
    s.x += b.x; s.y += b.y; s.z += b.z; s.w += b.w;
    if (resid) {
        float4 rv = ((const float4*)resid)[(size_t)n*Fout4 + o4];
        s.x += rv.x; s.y += rv.y; s.z += rv.z; s.w += rv.w;
    }
    ((float4*)out)[(size_t)n*Fout4 + o4] = s;
}

// ---------------- BN batch statistics: two stage ----------------
__global__ void bn_stats1_kernel(const float* __restrict__ X) {
    int tx = threadIdx.x & 31, ty = threadIdx.x >> 5;
    int c = blockIdx.x*32 + tx;
    int n0 = blockIdx.y*512;
    float s = 0.f, sq = 0.f;
    for (int n = n0 + ty; n < n0 + 512; n += 8) {
        float v = X[(size_t)n*HDIM + c];
        s += v; sq += v*v;
    }
    __shared__ float sh1[8][32], sh2[8][32];
    sh1[ty][tx] = s; sh2[ty][tx] = sq;
    __syncthreads();
    if (ty == 0) {
        #pragma unroll
        for (int k = 1; k < 8; k++) { s += sh1[k][tx]; sq += sh2[k][tx]; }
        g_bnp[0][blockIdx.y][c] = s;
        g_bnp[1][blockIdx.y][c] = sq;
    }
}
__global__ void bn_stats2_kernel() {
    int c = threadIdx.x;
    float s = 0.f, sq = 0.f;
    #pragma unroll
    for (int k = 0; k < 8; k++) { s += g_bnp[0][k][c]; sq += g_bnp[1][k][c]; }
    float mu = s / (float)NN;
    g_mu[c]  = mu;
    g_var[c] = sq / (float)NN - mu*mu;
}

// ---------------- fused BN apply + LayerNorm + ELU ----------------
__global__ void bn_ln_elu_kernel(const float* __restrict__ pre,
                                 const float* __restrict__ bg, const float* __restrict__ bb,
                                 const float* __restrict__ lg, const float* __restrict__ lb,
                                 float* __restrict__ out)
{
    int n = blockIdx.x, c = threadIdx.x;
    float x = pre[(size_t)n*HDIM + c];
    x = (x - g_mu[c]) * rsqrtf(g_var[c] + 1e-5f) * bg[c] + bb[c];
    float s1 = x, s2 = x*x;
    #pragma unroll
    for (int o = 16; o > 0; o >>= 1) {
        s1 += __shfl_xor_sync(0xffffffffu, s1, o);
        s2 += __shfl_xor_sync(0xffffffffu, s2, o);
    }
    __shared__ float a1[8], a2[8];
    if ((c & 31) == 0) { a1[c>>5] = s1; a2[c>>5] = s2; }
    __syncthreads();
    s1 = 0.f; s2 = 0.f;
    #pragma unroll
    for (int k = 0; k < 8; k++) { s1 += a1[k]; s2 += a2[k]; }
    float m = s1 * (1.f/256.f);
    float v = s2 * (1.f/256.f) - m*m;
    x = (x - m) * rsqrtf(v + 1e-5f) * lg[c] + lb[c];
    out[(size_t)n*HDIM + c] = (x > 0.f) ? x : expm1f(x);
}

// ---------------- launch ----------------
extern "C" void kernel_launch(void* const* d_in, const int* in_sizes, int n_in,
                              void* d_out, int out_size) {
    const float* X    = (const float*)d_in[0];
    const float* H    = (const float*)d_in[1];
    const float* W1   = (const float*)d_in[2];
    const float* W2   = (const float*)d_in[3];
    const float* W3   = (const float*)d_in[4];
    const float* imp  = (const float*)d_in[5];
    const float* b1   = (const float*)d_in[6];
    const float* b2   = (const float*)d_in[7];
    const float* b3   = (const float*)d_in[8];
    const float* bng  = (const float*)d_in[9];
    const float* bnb  = (const float*)d_in[10];
    const float* lng  = (const float*)d_in[11];
    const float* lnb  = (const float*)d_in[12];
    const float* rel  = (const float*)d_in[13];
    float* out = (float*)d_out;

    float *pDv, *pCE, *pSig;
    float4 *pXs, *pT, *pHn, *pPre, *pH, *pPart;
    unsigned *pMN, *pME;
    cudaGetSymbolAddress((void**)&pDv, g_dv);
    cudaGetSymbolAddress((void**)&pCE, g_cE);
    cudaGetSymbolAddress((void**)&pSig,g_sig);
    cudaGetSymbolAddress((void**)&pXs, g_Xs);
    cudaGetSymbolAddress((void**)&pT,  g_T);
    cudaGetSymbolAddress((void**)&pHn, g_Hn);
    cudaGetSymbolAddress((void**)&pPre,g_pre);
    cudaGetSymbolAddress((void**)&pH,  g_h);
    cudaGetSymbolAddress((void**)&pPart,g_part);
    cudaGetSymbolAddress((void**)&pMN, g_maskN);
    cudaGetSymbolAddress((void**)&pME, g_maskE);
    float* pGPart = (float*)pPart;

    // ---- structure precompute ----
    prep_kernel<<<1, 32>>>(rel, imp);
    build_maskN_kernel<<<RR*NN/8, 256>>>(H);
    transpose_mask_kernel<<<RR*(NN/32)*(EE/32)/8, 256>>>();
    build_cE_kernel<<<RR*EE/8, 256>>>();

    const int tE = EE/128, tN = NN/128;   // 16, 32

    // ---- layer 1 (cols = 128) ----
    prescale_kernel<<<RR*NN*32/256, 256>>>((const float4*)X, 32, 5, pXs);
    gather_kernel<<<dim3(RR*tE, 1, 4), 512>>>(pME, EE, NW, pXs, NN*64, 64, NW/4, nullptr, nullptr);
    combine_kernel<<<RR*EE*32/256, 256>>>(4, RR*EE, 5, pCE, pT);
    gather_kernel<<<dim3(RR*tN, 1, 2), 512>>>(pMN, NN, EW, pT, EE*64, 64, EW/2, nullptr, nullptr);
    combine_kernel<<<RR*NN*32/256, 256>>>(2, RR*NN, 5, pDv, pHn);
    gemm_kernel<<<dim3(NN/128, HDIM/64, RR), 256>>>((const float*)pHn, FF, HDIM, W1, pGPart);
    gemm_combine_kernel<<<NN*(HDIM/4)/256, 256>>>(pGPart, HDIM/4, pSig + 0*RR, b1, nullptr, (float*)pPre);
    bn_stats1_kernel<<<dim3(HDIM/32, 8), 256>>>((const float*)pPre);
    bn_stats2_kernel<<<1, HDIM>>>();
    bn_ln_elu_kernel<<<NN, HDIM>>>((const float*)pPre, bng, bnb, lng, lnb, (float*)pH);

    // ---- layer 2 (cols = 256) ----
    prescale_kernel<<<RR*NN*64/256, 256>>>(pH, 64, 6, pXs);
    gather_kernel<<<dim3(RR*tE, 2, 2), 512>>>(pME, EE, NW, pXs, NN*64, 64, NW/2, nullptr, nullptr);
    combine_kernel<<<RR*EE*64/256, 256>>>(2, RR*EE, 6, pCE, pT);
    gather_kernel<<<dim3(RR*tN, 2, 1), 512>>>(pMN, NN, EW, pT, EE*64, 64, EW, pDv, pHn);
    gemm_kernel<<<dim3(NN/128, HDIM/64, RR), 256>>>((const float*)pHn, HDIM, HDIM, W2, pGPart);
    gemm_combine_kernel<<<NN*(HDIM/4)/256, 256>>>(pGPart, HDIM/4, pSig + 1*RR, b2, nullptr, (float*)pPre);
    bn_stats1_kernel<<<dim3(HDIM/32, 8), 256>>>((const float*)pPre);
    bn_stats2_kernel<<<1, HDIM>>>();
    bn_ln_elu_kernel<<<NN, HDIM>>>((const float*)pPre, bng + HDIM, bnb + HDIM, lng + HDIM, lnb + HDIM, (float*)pH);

    // ---- layer 3 (cols = 256) + residual ----
    prescale_kernel<<<RR*NN*64/256, 256>>>(pH, 64, 6, pXs);
    gather_kernel<<<dim3(RR*tE, 2, 2), 512>>>(pME, EE, NW, pXs, NN*64, 64, NW/2, nullptr, nullptr);
    combine_kernel<<<RR*EE*64/256, 256>>>(2, RR*EE, 6, pCE, pT);
    gather_kernel<<<dim3(RR*tN, 2, 1), 512>>>(pMN, NN, EW, pT, EE*64, 64, EW, pDv, pHn);
    gemm_kernel<<<dim3(NN/128, FF/64, RR), 256>>>((const float*)pHn, HDIM, FF, W3, pGPart);
    gemm_combine_kernel<<<NN*(FF/4)/256, 256>>>(pGPart, FF/4, pSig + 2*RR, b3, X, out);
}

// round 7
// speedup vs baseline: 1.6497x; 1.0162x over previous
#include <cuda_runtime.h>
#include <cuda_pipeline.h>
#include <math.h>

#define RR 4
#define NN 4096
#define EE 2048
#define FF 128
#define HDIM 256
#define EW (EE/32)
#define NW (NN/32)
#define PART_S4 (RR*NN*64)

// ---------------- device scratch ----------------
__device__ float    g_rw[RR];
__device__ float    g_sig[3][RR];
__device__ float    g_dv[RR*NN];
__device__ float    g_cE[RR*EE];
__device__ unsigned g_maskN[(size_t)RR*NN*EW];
__device__ unsigned g_maskE[(size_t)RR*EE*NW];
__device__ float4   g_Xs [(size_t)RR*NN*64];
__device__ float4   g_T  [(size_t)RR*EE*64];
__device__ float4   g_Hn [(size_t)RR*NN*64];
__device__ float4   g_pre[(size_t)NN*64];
__device__ float4   g_part[(size_t)4*PART_S4];
__device__ float    g_mu[HDIM], g_var[HDIM];
__device__ float    g_bnp[2][8][HDIM];

// ---------------- prep ----------------
__global__ void prep_kernel(const float* __restrict__ rel, const float* __restrict__ imp) {
    if (threadIdx.x == 0) {
        float m = -1e30f;
        for (int r = 0; r < RR; r++) m = fmaxf(m, rel[r]);
        float e[RR], s = 0.f;
        for (int r = 0; r < RR; r++) { e[r] = expf(rel[r] - m); s += e[r]; }
        for (int r = 0; r < RR; r++) g_rw[r] = e[r] / s;
        for (int l = 0; l < 3; l++)
            for (int r = 0; r < RR; r++)
                g_sig[l][r] = 1.f / (1.f + expf(-imp[l*RR + r]));
    }
}

// ---------------- bitmask build ----------------
__global__ void build_maskN_kernel(const float* __restrict__ H) {
    int gw   = blockIdx.x * (blockDim.x >> 5) + (threadIdx.x >> 5);
    int lane = threadIdx.x & 31;
    if (gw >= RR*NN) return;
    int r = gw / NN;
    const float* row = H + (size_t)gw * EE;
    unsigned w0 = 0, w1 = 0;
    int cnt = 0;
    #pragma unroll 8
    for (int k = 0; k < 64; k++) {
        float v = row[k*32 + lane];
        unsigned b = __ballot_sync(0xffffffffu, v != 0.0f);
        cnt += (v != 0.0f) ? 1 : 0;
        if (k == lane)      w0 = b;
        if (k == lane + 32) w1 = b;
    }
    g_maskN[(size_t)gw*EW + lane]      = w0;
    g_maskN[(size_t)gw*EW + 32 + lane] = w1;
    int tot = __reduce_add_sync(0xffffffffu, cnt);
    if (lane == 0)
        g_dv[gw] = 1.0f / sqrtf(g_rw[r] * (float)tot + 1e-8f);
}

// ---------------- 32x32 bit transpose ----------------
__global__ void transpose_mask_kernel() {
    const int tilesPerR = (NN/32)*(EE/32);
    int gw   = blockIdx.x * (blockDim.x >> 5) + (threadIdx.x >> 5);
    int lane = threadIdx.x & 31;
    if (gw >= RR * tilesPerR) return;
    int r   = gw / tilesPerR;
    int rem = gw % tilesPerR;
    int nb  = rem / (EE/32);
    int eb  = rem % (EE/32);
    unsigned w = g_maskN[((size_t)r*NN + nb*32 + lane)*EW + eb];
    unsigned out = 0;
    #pragma unroll
    for (int j = 0; j < 32; j++) {
        unsigned b = __ballot_sync(0xffffffffu, (w >> j) & 1u);
        if (lane == j) out = b;
    }
    g_maskE[((size_t)r*EE + eb*32 + lane)*NW + nb] = out;
}

// ---------------- edge constants ----------------
__global__ void build_cE_kernel() {
    int gw   = blockIdx.x * (blockDim.x >> 5) + (threadIdx.x >> 5);
    int lane = threadIdx.x & 31;
    if (gw >= RR*EE) return;
    int r = gw / EE;
    const unsigned* row = g_maskE + (size_t)gw * NW;
    int cnt = 0;
    for (int k = lane; k < NW; k += 32) cnt += __popc(row[k]);
    cnt = __reduce_add_sync(0xffffffffu, cnt);
    if (lane == 0) {
        float rw = g_rw[r];
        g_cE[gw] = rw * rw / (rw * (float)cnt + 1e-8f);
    }
}

// ---------------- pre-scale source by dv (layer 1: from X) ----------------
__global__ void prescale_kernel(const float4* __restrict__ src, int srcStride4, int cshift,
                                float4* __restrict__ dst) {
    int idx = blockIdx.x*256 + threadIdx.x;
    int c  = idx & ((1<<cshift)-1);
    int rn = idx >> cshift;
    int n  = rn & (NN-1);
    float  s = g_dv[rn];
    float4 v = src[(size_t)n*srcStride4 + c];
    dst[((size_t)rn<<6) + c] = make_float4(s*v.x, s*v.y, s*v.z, s*v.w);
}

// ---------------- pipelined masked gather-SpMM: 512 thr, 128 targets, 4-stage, f32x2 ----------------
__global__ void __launch_bounds__(512) gather_kernel(
    const unsigned* __restrict__ mask, int Tn, int Sw,
    const float4* __restrict__ src, int relStride4, int srcRowStride4,
    int chunksPerP,
    const float* __restrict__ outScale,
    float4* __restrict__ out)
{
    __shared__ float4 sbuf[4*1024];   // 4 stages x 32 rows x 32 float4 = 64KB

    const int tid  = threadIdx.x, lane = tid & 31, w = tid >> 5;  // 16 warps
    const int tilesT = Tn >> 7;
    const int r  = blockIdx.x / tilesT;
    const int t0 = (blockIdx.x % tilesT) << 7;
    const int p  = blockIdx.z;
    const int colIdx4 = (blockIdx.y << 5) + lane;
    const float4* srcB = src + (size_t)r*relStride4 + (blockIdx.y << 5);
    const int wordBase = p * chunksPerP;
    const int rowBase  = wordBase << 5;
    const unsigned* mbase = mask + ((size_t)(r*Tn + t0 + (w<<3)))*Sw + wordBase;

    auto stage = [&](int c) {
        int st = c & 3;
        int gbase = rowBase + (c << 5);
        #pragma unroll
        for (int k = 0; k < 2; k++) {
            int i = tid + (k << 9);
            int row = i >> 5, col = i & 31;
            __pipeline_memcpy_async(&sbuf[(st<<10) + (row<<5) + col],
                                    srcB + (size_t)(gbase+row)*srcRowStride4 + col, 16);
        }
        __pipeline_commit();
    };

    unsigned long long accA[8], accB[8];   // packed f32x2 accumulators (4 floats/target)
    #pragma unroll
    for (int j = 0; j < 8; j++) { accA[j] = 0ull; accB[j] = 0ull; }

    stage(0); stage(1); stage(2);
    for (int c = 0; c < chunksPerP; c++) {
        __pipeline_wait_prior(2);
        __syncthreads();
        if (c + 3 < chunksPerP) stage(c+3);
        else                    __pipeline_commit();
        const ulonglong2* bufc = (const ulonglong2*)(sbuf + ((c & 3) << 10));
        #pragma unroll
        for (int j = 0; j < 8; j++) {
            unsigned b = mbase[(size_t)j*Sw + c];
            while (b) {
                int s = __ffs(b) - 1; b &= b - 1;
                ulonglong2 v = bufc[(s << 5) + lane];
                asm("add.rn.f32x2 %0, %0, %1;" : "+l"(accA[j]) : "l"(v.x));
                asm("add.rn.f32x2 %0, %0, %1;" : "+l"(accB[j]) : "l"(v.y));
            }
        }
    }

    float4* dst = outScale ? out : (g_part + (size_t)p * PART_S4);
    #pragma unroll
    for (int j = 0; j < 8; j++) {
        int t = t0 + (w<<3) + j;
        size_t o = ((size_t)(r*Tn + t) << 6) + colIdx4;
        float4 v = make_float4(
            __uint_as_float((unsigned)(accA[j] & 0xffffffffu)),
            __uint_as_float((unsigned)(accA[j] >> 32)),
            __uint_as_float((unsigned)(accB[j] & 0xffffffffu)),
            __uint_as_float((unsigned)(accB[j] >> 32)));
        if (outScale) {
            float sc = outScale[r*Tn + t];
            v.x *= sc; v.y *= sc; v.z *= sc; v.w *= sc;
        }
        dst[o] = v;
    }
}

// ---------------- combine gather partials ----------------
__global__ void combine_kernel(int P, int nRows, int cshift,
                               const float* __restrict__ scale, float4* __restrict__ out) {
    int idx = blockIdx.x*256 + threadIdx.x;
    int row = idx >> cshift;
    if (row >= nRows) return;
    int c = idx & ((1<<cshift)-1);
    size_t o = ((size_t)row << 6) + c;
    float4 s = g_part[o];
    for (int p = 1; p < P; p++) {
        float4 v = g_part[(size_t)p*PART_S4 + o];
        s.x += v.x; s.y += v.y; s.z += v.z; s.w += v.w;
    }
    float sc = scale[row];
    out[o] = make_float4(sc*s.x, sc*s.y, sc*s.z, sc*s.w);
}

// ---------------- per-relation projection GEMM (128x64 tile, r = blockIdx.z) ----------------
__global__ void __launch_bounds__(256) gemm_kernel(
    const float* __restrict__ A, int Fin, int Fout,
    const float* __restrict__ W,
    float* __restrict__ part)
{
    __shared__ float sA[16][132];
    __shared__ float sB[16][72];
    const int n0 = blockIdx.x << 7, o0 = blockIdx.y << 6;
    const int rr = blockIdx.z;
    const int tid = threadIdx.x;
    const int tx = tid & 15, ty = tid >> 4;

    const int aRow = tid >> 1, aOff = (tid & 1) << 3;
    const int bRow = tid >> 4, bCol = (tid & 15) << 2;

    const float* Ar = A + (size_t)rr*NN*HDIM;
    const float* Wr = W + (size_t)rr*Fin*Fout;

    float acc[8][4];
    #pragma unroll
    for (int i = 0; i < 8; i++)
        #pragma unroll
        for (int j = 0; j < 4; j++) acc[i][j] = 0.f;

    const int nTiles = Fin >> 4;

    float4 aReg0, aReg1, bReg;
    {
        const float* Ap = Ar + (size_t)(n0+aRow)*HDIM + aOff;
        aReg0 = *(const float4*)Ap;
        aReg1 = *(const float4*)(Ap + 4);
        bReg  = *(const float4*)&Wr[(size_t)bRow*Fout + o0 + bCol];
    }

    for (int t = 0; t < nTiles; t++) {
        sA[aOff+0][aRow] = aReg0.x; sA[aOff+1][aRow] = aReg0.y;
        sA[aOff+2][aRow] = aReg0.z; sA[aOff+3][aRow] = aReg0.w;
        sA[aOff+4][aRow] = aReg1.x; sA[aOff+5][aRow] = aReg1.y;
        sA[aOff+6][aRow] = aReg1.z; sA[aOff+7][aRow] = aReg1.w;
        *(float4*)&sB[bRow][bCol] = bReg;
        __syncthreads();
        if (t + 1 < nTiles) {
            int f2 = (t + 1) << 4;
            const float* Ap = Ar + (size_t)(n0+aRow)*HDIM + f2 + aOff;
            aReg0 = *(const float4*)Ap;
            aReg1 = *(const float4*)(Ap + 4);
            bReg  = *(const float4*)&Wr[(size_t)(f2+bRow)*Fout + o0 + bCol];
        }
        #pragma unroll
        for (int k = 0; k < 16; k++) {
            float4 a0 = *(const float4*)&sA[k][ty*8];
            float4 a1 = *(const float4*)&sA[k][ty*8+4];
            float4 bv = *(const float4*)&sB[k][tx*4];
            float av[8] = {a0.x,a0.y,a0.z,a0.w,a1.x,a1.y,a1.z,a1.w};
            float bb[4] = {bv.x,bv.y,bv.z,bv.w};
            #pragma unroll
            for (int i = 0; i < 8; i++)
                #pragma unroll
                for (int j = 0; j < 4; j++)
                    acc[i][j] += av[i] * bb[j];
        }
        __syncthreads();
    }

    float* dst = part + (size_t)rr*NN*256;
    #pragma unroll
    for (int i = 0; i < 8; i++) {
        int n = n0 + ty*8 + i;
        #pragma unroll
        for (int j = 0; j < 4; j++) {
            int o = o0 + tx*4 + j;
            dst[(size_t)n*Fout + o] = acc[i][j];
        }
    }
}

// ---------------- gemm combine: out = sum_r sig[r]*part[r] + bias (+resid) ----------------
__global__ void gemm_combine_kernel(const float* __restrict__ part, int Fout4,
                                    const float* __restrict__ sig,
                                    const float* __restrict__ bias,
                                    const float* __restrict__ resid,
                                    float* __restrict__ out)
{
    int idx = blockIdx.x*256 + threadIdx.x;
    int o4 = idx % Fout4, n = idx / Fout4;
    float4 s = make_float4(0.f,0.f,0.f,0.f);
    #pragma unroll
    for (int r = 0; r < RR; r++) {
        float sr = sig[r];
        float4 v = *(const float4*)&part[(size_t)r*NN*256 + (size_t)n*(Fout4*4) + o4*4];
        s.x += sr*v.x; s.y += sr*v.y; s.z += sr*v.z; s.w += sr*v.w;
    }
    float4 b = ((const float4*)bias)[o4];
    s.x += b.x; s.y += b.y; s.z += b.z; s.w += b.w;
    if (resid) {
        float4 rv = ((const float4*)resid)[(size_t)n*Fout4 + o4];
        s.x += rv.x; s.y += rv.y; s.z += rv.z; s.w += rv.w;
    }
    ((float4*)out)[(size_t)n*Fout4 + o4] = s;
}

// ---------------- BN batch statistics: two stage ----------------
__global__ void bn_stats1_kernel(const float* __restrict__ X) {
    int tx = threadIdx.x & 31, ty = threadIdx.x >> 5;
    int c = blockIdx.x*32 + tx;
    int n0 = blockIdx.y*512;
    float s = 0.f, sq = 0.f;
    for (int n = n0 + ty; n < n0 + 512; n += 8) {
        float v = X[(size_t)n*HDIM + c];
        s += v; sq += v*v;
    }
    __shared__ float sh1[8][32], sh2[8][32];
    sh1[ty][tx] = s; sh2[ty][tx] = sq;
    __syncthreads();
    if (ty == 0) {
        #pragma unroll
        for (int k = 1; k < 8; k++) { s += sh1[k][tx]; sq += sh2[k][tx]; }
        g_bnp[0][blockIdx.y][c] = s;
        g_bnp[1][blockIdx.y][c] = sq;
    }
}
__global__ void bn_stats2_kernel() {
    int c = threadIdx.x;
    float s = 0.f, sq = 0.f;
    #pragma unroll
    for (int k = 0; k < 8; k++) { s += g_bnp[0][k][c]; sq += g_bnp[1][k][c]; }
    float mu = s / (float)NN;
    g_mu[c]  = mu;
    g_var[c] = sq / (float)NN - mu*mu;
}

// ---------------- fused BN apply + LayerNorm + ELU + dv-prescale (4 relation copies) ----------------
__global__ void bn_ln_elu_scale_kernel(const float* __restrict__ pre,
                                       const float* __restrict__ bg, const float* __restrict__ bb,
                                       const float* __restrict__ lg, const float* __restrict__ lb,
                                       float* __restrict__ xs)
{
    int n = blockIdx.x, c = threadIdx.x;
    float x = pre[(size_t)n*HDIM + c];
    x = (x - g_mu[c]) * rsqrtf(g_var[c] + 1e-5f) * bg[c] + bb[c];
    float s1 = x, s2 = x*x;
    #pragma unroll
    for (int o = 16; o > 0; o >>= 1) {
        s1 += __shfl_xor_sync(0xffffffffu, s1, o);
        s2 += __shfl_xor_sync(0xffffffffu, s2, o);
    }
    __shared__ float a1[8], a2[8];
    if ((c & 31) == 0) { a1[c>>5] = s1; a2[c>>5] = s2; }
    __syncthreads();
    s1 = 0.f; s2 = 0.f;
    #pragma unroll
    for (int k = 0; k < 8; k++) { s1 += a1[k]; s2 += a2[k]; }
    float m = s1 * (1.f/256.f);
    float v = s2 * (1.f/256.f) - m*m;
    x = (x - m) * rsqrtf(v + 1e-5f) * lg[c] + lb[c];
    x = (x > 0.f) ? x : expm1f(x);
    #pragma unroll
    for (int r = 0; r < RR; r++)
        xs[(((size_t)r*NN + n) << 8) + c] = x * g_dv[r*NN + n];
}

// ---------------- launch ----------------
extern "C" void kernel_launch(void* const* d_in, const int* in_sizes, int n_in,
                              void* d_out, int out_size) {
    const float* X    = (const float*)d_in[0];
    const float* H    = (const float*)d_in[1];
    const float* W1   = (const float*)d_in[2];
    const float* W2   = (const float*)d_in[3];
    const float* W3   = (const float*)d_in[4];
    const float* imp  = (const float*)d_in[5];
    const float* b1   = (const float*)d_in[6];
    const float* b2   = (const float*)d_in[7];
    const float* b3   = (const float*)d_in[8];
    const float* bng  = (const float*)d_in[9];
    const float* bnb  = (const float*)d_in[10];
    const float* lng  = (const float*)d_in[11];
    const float* lnb  = (const float*)d_in[12];
    const float* rel  = (const float*)d_in[13];
    float* out = (float*)d_out;

    float *pDv, *pCE, *pSig;
    float4 *pXs, *pT, *pHn, *pPre, *pPart;
    unsigned *pMN, *pME;
    cudaGetSymbolAddress((void**)&pDv, g_dv);
    cudaGetSymbolAddress((void**)&pCE, g_cE);
    cudaGetSymbolAddress((void**)&pSig,g_sig);
    cudaGetSymbolAddress((void**)&pXs, g_Xs);
    cudaGetSymbolAddress((void**)&pT,  g_T);
    cudaGetSymbolAddress((void**)&pHn, g_Hn);
    cudaGetSymbolAddress((void**)&pPre,g_pre);
    cudaGetSymbolAddress((void**)&pPart,g_part);
    cudaGetSymbolAddress((void**)&pMN, g_maskN);
    cudaGetSymbolAddress((void**)&pME, g_maskE);
    float* pGPart = (float*)pPart;

    // ---- structure precompute ----
    prep_kernel<<<1, 32>>>(rel, imp);
    build_maskN_kernel<<<RR*NN/8, 256>>>(H);
    transpose_mask_kernel<<<RR*(NN/32)*(EE/32)/8, 256>>>();
    build_cE_kernel<<<RR*EE/8, 256>>>();

    const int tE = EE/128, tN = NN/128;   // 16, 32

    // ---- layer 1 (cols = 128) ----
    prescale_kernel<<<RR*NN*32/256, 256>>>((const float4*)X, 32, 5, pXs);
    gather_kernel<<<dim3(RR*tE, 1, 4), 512>>>(pME, EE, NW, pXs, NN*64, 64, NW/4, nullptr, nullptr);
    combine_kernel<<<RR*EE*32/256, 256>>>(4, RR*EE, 5, pCE, pT);
    gather_kernel<<<dim3(RR*tN, 1, 2), 512>>>(pMN, NN, EW, pT, EE*64, 64, EW/2, nullptr, nullptr);
    combine_kernel<<<RR*NN*32/256, 256>>>(2, RR*NN, 5, pDv, pHn);
    gemm_kernel<<<dim3(NN/128, HDIM/64, RR), 256>>>((const float*)pHn, FF, HDIM, W1, pGPart);
    gemm_combine_kernel<<<NN*(HDIM/4)/256, 256>>>(pGPart, HDIM/4, pSig + 0*RR, b1, nullptr, (float*)pPre);
    bn_stats1_kernel<<<dim3(HDIM/32, 8), 256>>>((const float*)pPre);
    bn_stats2_kernel<<<1, HDIM>>>();
    bn_ln_elu_scale_kernel<<<NN, HDIM>>>((const float*)pPre, bng, bnb, lng, lnb, (float*)pXs);

    // ---- layer 2 (cols = 256) ----
    gather_kernel<<<dim3(RR*tE, 2, 2), 512>>>(pME, EE, NW, pXs, NN*64, 64, NW/2, nullptr, nullptr);
    combine_kernel<<<RR*EE*64/256, 256>>>(2, RR*EE, 6, pCE, pT);
    gather_kernel<<<dim3(RR*tN, 2, 1), 512>>>(pMN, NN, EW, pT, EE*64, 64, EW, pDv, pHn);
    gemm_kernel<<<dim3(NN/128, HDIM/64, RR), 256>>>((const float*)pHn, HDIM, HDIM, W2, pGPart);
    gemm_combine_kernel<<<NN*(HDIM/4)/256, 256>>>(pGPart, HDIM/4, pSig + 1*RR, b2, nullptr, (float*)pPre);
    bn_stats1_kernel<<<dim3(HDIM/32, 8), 256>>>((const float*)pPre);
    bn_stats2_kernel<<<1, HDIM>>>();
    bn_ln_elu_scale_kernel<<<NN, HDIM>>>((const float*)pPre, bng + HDIM, bnb + HDIM, lng + HDIM, lnb + HDIM, (float*)pXs);

    // ---- layer 3 (cols = 256) + residual ----
    gather_kernel<<<dim3(RR*tE, 2, 2), 512>>>(pME, EE, NW, pXs, NN*64, 64, NW/2, nullptr, nullptr);
    combine_kernel<<<RR*EE*64/256, 256>>>(2, RR*EE, 6, pCE, pT);
    gather_kernel<<<dim3(RR*tN, 2, 1), 512>>>(pMN, NN, EW, pT, EE*64, 64, EW, pDv, pHn);
    gemm_kernel<<<dim3(NN/128, FF/64, RR), 256>>>((const float*)pHn, HDIM, FF, W3, pGPart);
    gemm_combine_kernel<<<NN*(FF/4)/256, 256>>>(pGPart, FF/4, pSig + 2*RR, b3, X, out);
}